// round 1
// baseline (speedup 1.0000x reference)
#include <cuda_runtime.h>
#include <cuda_bf16.h>
#include <math.h>

// Problem constants
#define BB   64        // batches
#define NN   64        // nodes per batch
#define HH   128       // hidden
#define NT   4096      // total nodes (BB*NN)
#define EPG  2048
#define EE   131072    // BB*EPG edges
#define ETOT 135168    // EE + NT (self loops)
#define KK   52        // ceil(0.8*64)
#define NK   3328      // BB*KK
#define NEG  0.01f

// ---------------- scratch (single blob, no allocations) ----------------
// offsets in floats
#define OFF_DEG    0
#define OFF_DINV   (OFF_DEG  + NT)
#define OFF_M      (OFF_DINV + NT)            // [b][c][r] hop matrix
#define OFF_CNT    (OFF_M    + BB*NN*NN)      // [b][r][c] multiplicity
#define OFF_S      (OFF_CNT  + BB*NN*NN)      // [b][r][c] E matrix
#define OFF_QT     (OFF_S    + BB*NN*NN)
#define OFF_XQ     (OFF_QT   + NT*HH)
#define OFF_TMP    (OFF_XQ   + NT*HH)
#define OFF_A      (OFF_TMP  + NT*HH)
#define OFF_H1     (OFF_A    + NT*HH)
#define OFF_H2     (OFF_H1   + NT*2*HH)
#define OFF_HCAT   (OFF_H2   + NT*HH)
#define OFF_AGG    (OFF_HCAT + NT*4*HH)
#define OFF_XC     (OFF_AGG  + NT*HH)
#define OFF_LOGIT  (OFF_XC   + NT*HH)
#define OFF_F1     (OFF_LOGIT+ NT)
#define OFF_F2     (OFF_F1   + NT)
#define OFF_G1     (OFF_F2   + NT)
#define OFF_G2     (OFF_G1   + NT)
#define OFF_SCORE  (OFF_G2   + NT)
#define OFF_PERM   (OFF_SCORE+ NT)            // NK ints stored in float slots
#define SCRATCH_FLOATS (OFF_PERM + NK + 64)

__device__ float g_scratch[SCRATCH_FLOATS];

__device__ __forceinline__ float leaky(float v) { return v > 0.0f ? v : NEG * v; }

// ---------------- init: zero M/Cnt, deg = 1 (self loop weight) ----------------
__global__ void init_k(float* deg, float* M, float* Cnt) {
    int i  = blockIdx.x * blockDim.x + threadIdx.x;
    int st = gridDim.x * blockDim.x;
    for (int j = i; j < BB*NN*NN; j += st) { M[j] = 0.0f; Cnt[j] = 0.0f; }
    for (int j = i; j < NT; j += st) deg[j] = 1.0f;
}

// ---------------- degree accumulation over edges ----------------
__global__ void deg_k(const int* ei, const float* ew, float* deg) {
    int e = blockIdx.x * blockDim.x + threadIdx.x;
    if (e < EE) atomicAdd(&deg[ei[EE + e]], ew[e]);   // col = ei[1]
}

__global__ void dinv_k(const float* deg, float* dinv) {
    int i = blockIdx.x * blockDim.x + threadIdx.x;
    if (i < NT) {
        float d = deg[i];
        dinv[i] = d > 0.0f ? (1.0f / sqrtf(fmaxf(d, 1e-12f))) : 0.0f;
    }
}

// ---------------- scatter into dense per-batch M and Cnt ----------------
__global__ void scatter_k(const int* ei, const float* ewt,
                          const float* dinv, float* M, float* Cnt) {
    int t = blockIdx.x * blockDim.x + threadIdx.x;
    if (t >= ETOT) return;
    int r, c; float w;
    if (t < EE) { r = ei[t]; c = ei[EE + t]; w = ewt[t]; }
    else        { r = t - EE; c = r; w = 1.0f; }
    int b  = r >> 6;
    int rl = r & 63, cl = c & 63;
    float e = dinv[r] * w * dinv[c];
    atomicAdd(&M[b*4096 + cl*64 + rl], e);       // hop matrix [c][r]
    atomicAdd(&Cnt[b*4096 + rl*64 + cl], 1.0f);  // counts [r][c]
}

// ---------------- broadcast target_x per node ----------------
__global__ void qt_k(const float* tx, float* qt) {
    int i = blockIdx.x * blockDim.x + threadIdx.x;  // NT*HH
    int rnode = i >> 7, h = i & 127;
    qt[i] = tx[(rnode >> 6) * HH + h];
}

// ---------------- per-batch 64x64 @ 64x128 (hop / agg) ----------------
// TRANS=false: out[c][h] = sum_r M[c*64+r] * in[r][h]   (hop)
// TRANS=true : out[c][h] = sum_r S[r*64+c] * in[r][h]   (agg, S^T)
template<bool TRANS>
__global__ void hop_k(const float* Mt, const float* in, float* out) {
    __shared__ float Ms[4096];
    __shared__ float Xs[8192];
    int b = blockIdx.x, t = threadIdx.x;
    for (int i = t; i < 4096; i += 256) Ms[i] = Mt[b*4096 + i];
    for (int i = t; i < 8192; i += 256) Xs[i] = in[b*8192 + i];
    __syncthreads();
    for (int i = t; i < 8192; i += 256) {
        int c = i >> 7, h = i & 127;
        float acc = 0.0f;
        #pragma unroll
        for (int r = 0; r < 64; r++) {
            float m = TRANS ? Ms[r*64 + c] : Ms[c*64 + r];
            acc += m * Xs[r*128 + h];
        }
        out[b*8192 + i] = acc;
    }
}

// ---------------- fp32 GEMM: C[4096 x Nn] = act(A[4096 x K] @ W[K x Nn]) ----
// BM=128, BN=64, BK=16, 256 threads, 8x4 microtile
template<bool LEAKY>
__global__ void gemm_k(const float* __restrict__ A, const float* __restrict__ W,
                       float* __restrict__ C, int K, int Nn) {
    __shared__ float As[16][128];
    __shared__ float Ws[16][64];
    int tid = threadIdx.x;
    int rowBase = blockIdx.y * 128;
    int colBase = blockIdx.x * 64;
    int ty = tid >> 4, tx = tid & 15;
    float acc[8][4];
    #pragma unroll
    for (int i = 0; i < 8; i++)
        #pragma unroll
        for (int j = 0; j < 4; j++) acc[i][j] = 0.0f;

    for (int k0 = 0; k0 < K; k0 += 16) {
        #pragma unroll
        for (int i = 0; i < 8; i++) {
            int e = tid + i*256;       // 0..2047
            int m = e >> 4, kk = e & 15;
            As[kk][m] = A[(size_t)(rowBase + m) * K + k0 + kk];
        }
        #pragma unroll
        for (int i = 0; i < 4; i++) {
            int e = tid + i*256;       // 0..1023
            int kk = e >> 6, nn = e & 63;
            Ws[kk][nn] = W[(size_t)(k0 + kk) * Nn + colBase + nn];
        }
        __syncthreads();
        #pragma unroll
        for (int kk = 0; kk < 16; kk++) {
            float a[8], bv[4];
            #pragma unroll
            for (int i = 0; i < 8; i++) a[i] = As[kk][ty*8 + i];
            #pragma unroll
            for (int j = 0; j < 4; j++) bv[j] = Ws[kk][tx*4 + j];
            #pragma unroll
            for (int i = 0; i < 8; i++)
                #pragma unroll
                for (int j = 0; j < 4; j++) acc[i][j] += a[i] * bv[j];
        }
        __syncthreads();
    }
    #pragma unroll
    for (int i = 0; i < 8; i++)
        #pragma unroll
        for (int j = 0; j < 4; j++) {
            float v = acc[i][j];
            if (LEAKY) v = leaky(v);
            C[(size_t)(rowBase + ty*8 + i) * Nn + colBase + tx*4 + j] = v;
        }
}

// ---------------- hcat = [a, q, a-q, a*q] ----------------
__global__ void hcat_k(const float* a, const float* q, float* hc) {
    int i = blockIdx.x * blockDim.x + threadIdx.x;  // NT*HH
    int r = i >> 7, h = i & 127;
    float av = a[i], qv = q[i];
    float* o = hc + (size_t)r * 512;
    o[h]       = av;
    o[128 + h] = qv;
    o[256 + h] = av - qv;
    o[384 + h] = av * qv;
}

// ---------------- logit: leaky(h2 @ W3col) per row ----------------
__global__ void logit_k(const float* h2, const float* W3, float* out) {
    int r = blockIdx.x * 8 + (threadIdx.x >> 5);
    int lane = threadIdx.x & 31;
    float s = 0.0f;
    #pragma unroll
    for (int h = lane; h < 128; h += 32) s += h2[(size_t)r*128 + h] * W3[h];
    #pragma unroll
    for (int o = 16; o; o >>= 1) s += __shfl_xor_sync(0xFFFFFFFFu, s, o);
    if (lane == 0) out[r] = leaky(s);
}

// ---------------- per-batch softmax over 64 entries ----------------
__global__ void segsm_k(const float* in, float* out) {
    __shared__ float sh[64];
    int b = blockIdx.x, t = threadIdx.x;
    float v = in[b*64 + t];
    sh[t] = v; __syncthreads();
    for (int o = 32; o; o >>= 1) { if (t < o) sh[t] = fmaxf(sh[t], sh[t+o]); __syncthreads(); }
    float m = sh[0]; __syncthreads();
    float e = expf(v - m);
    sh[t] = e; __syncthreads();
    for (int o = 32; o; o >>= 1) { if (t < o) sh[t] += sh[t+o]; __syncthreads(); }
    out[b*64 + t] = e / sh[0];
}

// ---------------- build S (edge softmax over cols, weighted by counts) ------
__global__ void buildS_k(const float* f1, const float* f2, const float* Cnt, float* S) {
    __shared__ float Cs[4096], f1s[64], f2s[64];
    int b = blockIdx.x, t = threadIdx.x;  // 64 threads
    f1s[t] = f1[b*64 + t];
    f2s[t] = f2[b*64 + t];
    for (int i = t; i < 4096; i += 64) Cs[i] = Cnt[b*4096 + i];
    __syncthreads();
    int c = t;
    float m = -3.0e38f;
    for (int r = 0; r < 64; r++) {
        if (Cs[r*64 + c] > 0.0f) {
            float e = leaky(f1s[c] + f2s[r]);
            m = fmaxf(m, e);
        }
    }
    float d = 0.0f;
    for (int r = 0; r < 64; r++) {
        float cnt = Cs[r*64 + c];
        if (cnt > 0.0f) {
            float e = leaky(f1s[c] + f2s[r]);
            d += cnt * expf(e - m);
        }
    }
    for (int r = 0; r < 64; r++) {
        float cnt = Cs[r*64 + c];
        float v = 0.0f;
        if (cnt > 0.0f) {
            float e = leaky(f1s[c] + f2s[r]);
            v = cnt * expf(e - m) / d;
        }
        S[b*4096 + r*64 + c] = v;
    }
}

// ---------------- x_c = mean_h leaky(x + agg @ lin_W[h]) ----------------
__global__ void xc_k(const float* x, const float* t0, const float* t1, float* xc) {
    int i = blockIdx.x * blockDim.x + threadIdx.x;  // NT*HH
    float l0 = leaky(x[i] + t0[i]);
    float l1 = leaky(x[i] + t1[i]);
    xc[i] = 0.5f * (l0 + l1);
}

__global__ void sum_k(const float* a, const float* b, float* o) {
    int i = blockIdx.x * blockDim.x + threadIdx.x;
    if (i < NT) o[i] = a[i] + b[i];
}

// ---------------- per-batch top-52 (stable: lowest index wins ties) --------
__global__ void topk_k(const float* score, int* perm) {
    __shared__ float sv[64];
    __shared__ float rv[64];
    __shared__ int   ri[64];
    int b = blockIdx.x, t = threadIdx.x;
    sv[t] = score[b*64 + t];
    __syncthreads();
    for (int j = 0; j < KK; j++) {
        rv[t] = sv[t]; ri[t] = t;
        __syncthreads();
        for (int o = 32; o; o >>= 1) {
            if (t < o) {
                if (rv[t+o] > rv[t] || (rv[t+o] == rv[t] && ri[t+o] < ri[t])) {
                    rv[t] = rv[t+o]; ri[t] = ri[t+o];
                }
            }
            __syncthreads();
        }
        if (t == 0) { perm[b*KK + j] = b*64 + ri[0]; sv[ri[0]] = -3.0e38f; }
        __syncthreads();
    }
}

// ---------------- outputs ----------------
__global__ void xout_k(const float* x, const int* perm, const float* score, float* out) {
    int i = blockIdx.x * blockDim.x + threadIdx.x;  // NK*HH
    int p = perm[i >> 7];
    out[i] = x[(size_t)p * 128 + (i & 127)] * score[p];
}

__global__ void meta_k(const int* perm, float* bout, float* pout) {
    int i = blockIdx.x * blockDim.x + threadIdx.x;
    if (i < NK) {
        int p = perm[i];
        bout[i] = (float)(p >> 6);
        pout[i] = (float)p;
    }
}

// ---------------- A2 diagonal block: S_sel^T (A_d S_sel), diag=1 ----------
__global__ void A2_k(const float* Mt, const float* S, const int* perm, float* A2) {
    __shared__ float Ms[4096];
    __shared__ float Ss[4096];
    __shared__ float T[64*KK];
    __shared__ int idxs[KK];
    int b = blockIdx.x, t = threadIdx.x;  // 256 threads
    for (int i = t; i < 4096; i += 256) { Ms[i] = Mt[b*4096 + i]; Ss[i] = S[b*4096 + i]; }
    if (t < KK) idxs[t] = perm[b*KK + t] - b*64;
    __syncthreads();
    // T[r][j] = sum_c A_d[r][c] * S[c][idx_j] ; A_d[r][c] = Ms[c*64+r]
    for (int i = t; i < 64*KK; i += 256) {
        int r = i / KK, j = i - r*KK;
        int cj = idxs[j];
        float acc = 0.0f;
        #pragma unroll
        for (int c = 0; c < 64; c++) acc += Ms[c*64 + r] * Ss[c*64 + cj];
        T[r*KK + j] = acc;
    }
    __syncthreads();
    // A2[i][j] = sum_r S[r][idx_i] * T[r][j]; diag -> 1
    for (int o = t; o < KK*KK; o += 256) {
        int i = o / KK, j = o - i*KK;
        float v;
        if (i == j) v = 1.0f;
        else {
            int ci = idxs[i];
            v = 0.0f;
            #pragma unroll
            for (int r = 0; r < 64; r++) v += Ss[r*64 + ci] * T[r*KK + j];
        }
        A2[(size_t)(b*KK + i) * NK + (size_t)(b*KK + j)] = v;
    }
}

// =======================================================================
extern "C" void kernel_launch(void* const* d_in, const int* in_sizes, int n_in,
                              void* d_out, int out_size) {
    const float* x   = (const float*)d_in[0];
    const int*   ei  = (const int*)d_in[1];
    const float* ewt = (const float*)d_in[2];
    const float* tx  = (const float*)d_in[3];
    const float* Wk  = (const float*)d_in[5];
    const float* W1  = (const float*)d_in[6];
    const float* W2  = (const float*)d_in[7];
    const float* W3  = (const float*)d_in[8];
    const float* lW  = (const float*)d_in[9];
    float* out = (float*)d_out;

    float* base = nullptr;
    cudaGetSymbolAddress((void**)&base, g_scratch);

    float* p_deg   = base + OFF_DEG;
    float* p_dinv  = base + OFF_DINV;
    float* p_M     = base + OFF_M;
    float* p_Cnt   = base + OFF_CNT;
    float* p_S     = base + OFF_S;
    float* p_qt    = base + OFF_QT;
    float* p_xq    = base + OFF_XQ;
    float* p_tmp   = base + OFF_TMP;
    float* p_a     = base + OFF_A;
    float* p_h1    = base + OFF_H1;
    float* p_h2    = base + OFF_H2;
    float* p_hcat  = base + OFF_HCAT;
    float* p_agg   = base + OFF_AGG;
    float* p_xc    = base + OFF_XC;
    float* p_logit = base + OFF_LOGIT;
    float* p_f1    = base + OFF_F1;
    float* p_f2    = base + OFF_F2;
    float* p_g1    = base + OFF_G1;
    float* p_g2    = base + OFF_G2;
    float* p_score = base + OFF_SCORE;
    int*   p_perm  = (int*)(base + OFF_PERM);

    // ---- graph normalization + dense per-batch operators ----
    init_k<<<1024, 256>>>(p_deg, p_M, p_Cnt);
    deg_k<<<EE/256, 256>>>(ei, ewt, p_deg);
    dinv_k<<<NT/256, 256>>>(p_deg, p_dinv);
    scatter_k<<<ETOT/256, 256>>>(ei, ewt, p_dinv, p_M, p_Cnt);
    qt_k<<<NT*HH/256, 256>>>(tx, p_qt);

    // x_q = hop(hop(x))
    hop_k<false><<<BB, 256>>>(p_M, x, p_tmp);
    hop_k<false><<<BB, 256>>>(p_M, p_tmp, p_xq);

    // ---- attention helper ----
    auto att = [&](const float* kv, const float* q, int widx, float* fout) {
        gemm_k<false><<<dim3(2, 32), 256>>>(kv, Wk + (size_t)widx*HH*HH, p_a, HH, HH);
        hcat_k<<<NT*HH/256, 256>>>(p_a, q, p_hcat);
        gemm_k<true><<<dim3(4, 32), 256>>>(p_hcat, W1 + (size_t)widx*4*HH*2*HH, p_h1, 4*HH, 2*HH);
        gemm_k<true><<<dim3(2, 32), 256>>>(p_h1, W2 + (size_t)widx*2*HH*HH, p_h2, 2*HH, HH);
        logit_k<<<NT/8, 256>>>(p_h2, W3 + (size_t)widx*HH, p_logit);
        segsm_k<<<BB, 64>>>(p_logit, fout);
    };

    att(x, p_xq, 0, p_f1);
    att(x, p_qt, 1, p_f2);

    // E softmax (dense per batch) and aggregation
    buildS_k<<<BB, 64>>>(p_f1, p_f2, p_Cnt, p_S);
    hop_k<true><<<BB, 256>>>(p_S, x, p_agg);   // agg = S^T x per batch

    // x_c = mean over heads of leaky(x + agg @ lin_W[h])
    gemm_k<false><<<dim3(2, 32), 256>>>(p_agg, lW,                p_tmp, HH, HH);
    gemm_k<false><<<dim3(2, 32), 256>>>(p_agg, lW + (size_t)HH*HH, p_a,  HH, HH);
    xc_k<<<NT*HH/256, 256>>>(x, p_tmp, p_a, p_xc);

    // x_q2 = hop(hop(x_c))
    hop_k<false><<<BB, 256>>>(p_M, p_xc, p_tmp);
    hop_k<false><<<BB, 256>>>(p_M, p_tmp, p_xq);

    att(p_xc, p_xq, 2, p_g1);
    att(p_xc, p_qt, 3, p_g2);

    // cluster score + top-k
    sum_k<<<NT/256, 256>>>(p_g1, p_g2, p_logit);
    segsm_k<<<BB, 64>>>(p_logit, p_score);
    topk_k<<<BB, 64>>>(p_score, p_perm);

    // ---- outputs: [x_out (NK*H)] [A2 (NK*NK)] [batch_out (NK)] [perm (NK)] ----
    float* out_x    = out;
    float* out_A2   = out + (size_t)NK*HH;
    float* out_bat  = out + (size_t)NK*HH + (size_t)NK*NK;
    float* out_perm = out_bat + NK;

    xout_k<<<NK*HH/256, 256>>>(x, p_perm, p_score, out_x);
    meta_k<<<(NK + 255)/256, 256>>>(p_perm, out_bat, out_perm);
    cudaMemsetAsync(out_A2, 0, (size_t)NK*NK*sizeof(float));
    A2_k<<<BB, 256>>>(p_M, p_S, p_perm, out_A2);
}

// round 2
// speedup vs baseline: 2.0238x; 2.0238x over previous
#include <cuda_runtime.h>
#include <cuda_bf16.h>
#include <math.h>

// Problem constants
#define BB   64
#define NN   64
#define HH   128
#define NT   4096
#define EE   131072
#define ETOT 135168
#define KK   52
#define NK   3328
#define NEG  0.01f

// ---------------- scratch offsets (floats) ----------------
#define OFF_DEG    0
#define OFF_DINV   (OFF_DEG  + NT)
#define OFF_M      (OFF_DINV + NT)            // [b][c][r]
#define OFF_CNT    (OFF_M    + BB*NN*NN)      // [b][r][c]
#define OFF_S      (OFF_CNT  + BB*NN*NN)      // [b][r][c]
#define OFF_XQ     (OFF_S    + BB*NN*NN)
#define OFF_AGG    (OFF_XQ   + NT*HH)
#define OFF_XC     (OFF_AGG  + NT*HH)
#define OFF_HCAT   (OFF_XC   + NT*HH)         // 8192 x 512
#define OFF_H1     (OFF_HCAT + 2*NT*4*HH)     // 8192 x 256
#define OFF_H2     (OFF_H1   + 2*NT*2*HH)     // 8192 x 128
#define OFF_F1     (OFF_H2   + 2*NT*HH)
#define OFF_F2     (OFF_F1   + NT)
#define OFF_G1     (OFF_F2   + NT)
#define OFF_G2     (OFF_G1   + NT)
#define OFF_SCORE  (OFF_G2   + NT)
#define OFF_PERM   (OFF_SCORE+ NT)
#define SCRATCH_FLOATS (OFF_PERM + NK + 64)

__device__ float g_scratch[SCRATCH_FLOATS];

__device__ __forceinline__ float leaky(float v) { return v > 0.0f ? v : NEG * v; }

// ---------------- init ----------------
__global__ void init_k(float* deg, float* M, float* Cnt) {
    int i  = blockIdx.x * blockDim.x + threadIdx.x;
    int st = gridDim.x * blockDim.x;
    for (int j = i; j < BB*NN*NN; j += st) { M[j] = 0.0f; Cnt[j] = 0.0f; }
    for (int j = i; j < NT; j += st) deg[j] = 1.0f;
}

__global__ void deg_k(const int* ei, const float* ew, float* deg) {
    int e = blockIdx.x * blockDim.x + threadIdx.x;
    if (e < EE) atomicAdd(&deg[ei[EE + e]], ew[e]);
}

__global__ void dinv_k(const float* deg, float* dinv) {
    int i = blockIdx.x * blockDim.x + threadIdx.x;
    if (i < NT) {
        float d = deg[i];
        dinv[i] = d > 0.0f ? (1.0f / sqrtf(fmaxf(d, 1e-12f))) : 0.0f;
    }
}

__global__ void scatter_k(const int* ei, const float* ewt,
                          const float* dinv, float* M, float* Cnt) {
    int t = blockIdx.x * blockDim.x + threadIdx.x;
    if (t >= ETOT) return;
    int r, c; float w;
    if (t < EE) { r = ei[t]; c = ei[EE + t]; w = ewt[t]; }
    else        { r = t - EE; c = r; w = 1.0f; }
    int b  = r >> 6;
    int rl = r & 63, cl = c & 63;
    float e = dinv[r] * w * dinv[c];
    atomicAdd(&M[b*4096 + cl*64 + rl], e);       // M[c][r] = A_d[r][c]
    atomicAdd(&Cnt[b*4096 + rl*64 + cl], 1.0f);
}

// ---------------- fused two-hop: out = M @ (M @ in) per batch --------------
// grid (BB, 2): blockIdx.y selects h-half (64 cols)
__global__ __launch_bounds__(256) void hop2_k(const float* Mt, const float* in, float* out) {
    __shared__ float Ms[4096];
    __shared__ float Xs[64*64];   // [r][hlocal]
    int b = blockIdx.x, hb = blockIdx.y * 64, t = threadIdx.x;
    for (int i = t; i < 4096; i += 256) Ms[i] = Mt[b*4096 + i];
    for (int i = t; i < 4096; i += 256) {
        int r = i >> 6, h = i & 63;
        Xs[i] = in[b*8192 + r*128 + hb + h];
    }
    __syncthreads();
    float reg[16];
    #pragma unroll
    for (int s = 0; s < 16; s++) {
        int i = t + 256*s;
        int c = i >> 6, h = i & 63;
        float acc = 0.0f;
        #pragma unroll
        for (int r = 0; r < 64; r++) acc += Ms[c*64 + r] * Xs[r*64 + h];
        reg[s] = acc;
    }
    __syncthreads();
    #pragma unroll
    for (int s = 0; s < 16; s++) Xs[t + 256*s] = reg[s];
    __syncthreads();
    #pragma unroll
    for (int s = 0; s < 16; s++) {
        int i = t + 256*s;
        int c = i >> 6, h = i & 63;
        float acc = 0.0f;
        #pragma unroll
        for (int r = 0; r < 64; r++) acc += Ms[c*64 + r] * Xs[r*64 + h];
        out[b*8192 + c*128 + hb + h] = acc;
    }
}

// ---------------- agg = S^T x per batch ----------------
__global__ __launch_bounds__(256) void aggT_k(const float* St, const float* in, float* out) {
    __shared__ float Ms[4096];
    __shared__ float Xs[8192];
    int b = blockIdx.x, t = threadIdx.x;
    for (int i = t; i < 4096; i += 256) Ms[i] = St[b*4096 + i];
    for (int i = t; i < 8192; i += 256) Xs[i] = in[b*8192 + i];
    __syncthreads();
    for (int i = t; i < 8192; i += 256) {
        int c = i >> 7, h = i & 127;
        float acc = 0.0f;
        #pragma unroll
        for (int r = 0; r < 64; r++) acc += Ms[r*64 + c] * Xs[r*128 + h];
        out[b*8192 + i] = acc;
    }
}

// ---------------- batched fp32 GEMM over stacked halves --------------------
// C[8192 x Nn] = act(A' @ (W + half*Wstride)), half = rowBase>>12
// AWRAP: A has only 4096 rows (row & 4095)
// HCAT: epilogue writes [a, q, a-q, a*q] into C (stride 512), q from q0/txg
template<bool AWRAP, bool LEAKY, bool HCAT>
__global__ __launch_bounds__(256) void gemm8_k(
    const float* __restrict__ A, const float* __restrict__ W,
    float* __restrict__ C, int K, int Nn, int Wstride,
    const float* __restrict__ q0, const float* __restrict__ txg)
{
    __shared__ float As[16][128];
    __shared__ float Ws[16][64];
    int tid = threadIdx.x;
    int rowBase = blockIdx.y * 128;
    int colBase = blockIdx.x * 64;
    const float* Wp = W + (size_t)(rowBase >> 12) * Wstride;
    int ty = tid >> 4, txi = tid & 15;
    float acc[8][4];
    #pragma unroll
    for (int i = 0; i < 8; i++)
        #pragma unroll
        for (int j = 0; j < 4; j++) acc[i][j] = 0.0f;

    for (int k0 = 0; k0 < K; k0 += 16) {
        #pragma unroll
        for (int i = 0; i < 8; i++) {
            int e = tid + i*256;
            int m = e >> 4, kk = e & 15;
            int arow = AWRAP ? ((rowBase + m) & 4095) : (rowBase + m);
            As[kk][m] = A[(size_t)arow * K + k0 + kk];
        }
        #pragma unroll
        for (int i = 0; i < 4; i++) {
            int e = tid + i*256;
            int kk = e >> 6, nn = e & 63;
            Ws[kk][nn] = Wp[(size_t)(k0 + kk) * Nn + colBase + nn];
        }
        __syncthreads();
        #pragma unroll
        for (int kk = 0; kk < 16; kk++) {
            float a[8], bv[4];
            #pragma unroll
            for (int i = 0; i < 8; i++) a[i] = As[kk][ty*8 + i];
            #pragma unroll
            for (int j = 0; j < 4; j++) bv[j] = Ws[kk][txi*4 + j];
            #pragma unroll
            for (int i = 0; i < 8; i++)
                #pragma unroll
                for (int j = 0; j < 4; j++) acc[i][j] += a[i] * bv[j];
        }
        __syncthreads();
    }
    #pragma unroll
    for (int i = 0; i < 8; i++)
        #pragma unroll
        for (int j = 0; j < 4; j++) {
            int row = rowBase + ty*8 + i;
            int col = colBase + txi*4 + j;
            float v = acc[i][j];
            if (HCAT) {
                float qv;
                if (row < 4096) qv = q0[(row << 7) + col];
                else { int node = row - 4096; qv = txg[((node >> 6) << 7) + col]; }
                float* o = C + (size_t)row * 512 + col;
                o[0]   = v;
                o[128] = qv;
                o[256] = v - qv;
                o[384] = v * qv;
            } else {
                if (LEAKY) v = leaky(v);
                C[(size_t)row * Nn + col] = v;
            }
        }
}

// ---------------- fused logit + per-batch softmax --------------------------
// grid (BB, 2): half 0 -> out0, half 1 -> out1.  W3 indexed by half.
__global__ void logsm_k(const float* __restrict__ h2, const float* __restrict__ W3,
                        float* out0, float* out1) {
    __shared__ float sh[64];
    int b = blockIdx.x, half = blockIdx.y, t = threadIdx.x;
    int row = half*4096 + b*64 + t;
    const float4* hp = (const float4*)(h2 + (size_t)row * 128);
    const float4* wp = (const float4*)(W3 + half * 128);
    float s = 0.0f;
    #pragma unroll
    for (int i = 0; i < 32; i++) {
        float4 hv = hp[i], wv = wp[i];
        s += hv.x*wv.x + hv.y*wv.y + hv.z*wv.z + hv.w*wv.w;
    }
    s = leaky(s);
    float v = s;
    sh[t] = v; __syncthreads();
    for (int o = 32; o; o >>= 1) { if (t < o) sh[t] = fmaxf(sh[t], sh[t+o]); __syncthreads(); }
    float m = sh[0]; __syncthreads();
    float e = expf(v - m);
    sh[t] = e; __syncthreads();
    for (int o = 32; o; o >>= 1) { if (t < o) sh[t] += sh[t+o]; __syncthreads(); }
    (half ? out1 : out0)[b*64 + t] = e / sh[0];
}

// ---------------- cluster score = segsoftmax(g1+g2) ----------------
__global__ void score_k(const float* g1, const float* g2, float* out) {
    __shared__ float sh[64];
    int b = blockIdx.x, t = threadIdx.x;
    float v = g1[b*64 + t] + g2[b*64 + t];
    sh[t] = v; __syncthreads();
    for (int o = 32; o; o >>= 1) { if (t < o) sh[t] = fmaxf(sh[t], sh[t+o]); __syncthreads(); }
    float m = sh[0]; __syncthreads();
    float e = expf(v - m);
    sh[t] = e; __syncthreads();
    for (int o = 32; o; o >>= 1) { if (t < o) sh[t] += sh[t+o]; __syncthreads(); }
    out[b*64 + t] = e / sh[0];
}

// ---------------- build S ----------------
__global__ void buildS_k(const float* f1, const float* f2, const float* Cnt, float* S) {
    __shared__ float Cs[4096], f1s[64], f2s[64];
    int b = blockIdx.x, t = threadIdx.x;
    f1s[t] = f1[b*64 + t];
    f2s[t] = f2[b*64 + t];
    for (int i = t; i < 4096; i += 64) Cs[i] = Cnt[b*4096 + i];
    __syncthreads();
    int c = t;
    float m = -3.0e38f;
    for (int r = 0; r < 64; r++)
        if (Cs[r*64 + c] > 0.0f) m = fmaxf(m, leaky(f1s[c] + f2s[r]));
    float d = 0.0f;
    for (int r = 0; r < 64; r++) {
        float cnt = Cs[r*64 + c];
        if (cnt > 0.0f) d += cnt * expf(leaky(f1s[c] + f2s[r]) - m);
    }
    for (int r = 0; r < 64; r++) {
        float cnt = Cs[r*64 + c];
        float v = 0.0f;
        if (cnt > 0.0f) v = cnt * expf(leaky(f1s[c] + f2s[r]) - m) / d;
        S[b*4096 + r*64 + c] = v;
    }
}

// ---------------- x_c from two lin heads ----------------
__global__ void xc_k(const float* x, const float* t2, float* xc) {
    int i = blockIdx.x * blockDim.x + threadIdx.x;  // NT*HH
    float l0 = leaky(x[i] + t2[i]);
    float l1 = leaky(x[i] + t2[i + NT*HH]);
    xc[i] = 0.5f * (l0 + l1);
}

// ---------------- per-batch top-52 ----------------
__global__ void topk_k(const float* score, int* perm) {
    __shared__ float sv[64];
    __shared__ float rv[64];
    __shared__ int   ri[64];
    int b = blockIdx.x, t = threadIdx.x;
    sv[t] = score[b*64 + t];
    __syncthreads();
    for (int j = 0; j < KK; j++) {
        rv[t] = sv[t]; ri[t] = t;
        __syncthreads();
        for (int o = 32; o; o >>= 1) {
            if (t < o) {
                if (rv[t+o] > rv[t] || (rv[t+o] == rv[t] && ri[t+o] < ri[t])) {
                    rv[t] = rv[t+o]; ri[t] = ri[t+o];
                }
            }
            __syncthreads();
        }
        if (t == 0) { perm[b*KK + j] = b*64 + ri[0]; sv[ri[0]] = -3.0e38f; }
        __syncthreads();
    }
}

// ---------------- outputs ----------------
__global__ void xout_k(const float* x, const int* perm, const float* score, float* out) {
    int i = blockIdx.x * blockDim.x + threadIdx.x;
    int p = perm[i >> 7];
    out[i] = x[(size_t)p * 128 + (i & 127)] * score[p];
}

__global__ void meta_k(const int* perm, float* bout, float* pout) {
    int i = blockIdx.x * blockDim.x + threadIdx.x;
    if (i < NK) {
        int p = perm[i];
        bout[i] = (float)(p >> 6);
        pout[i] = (float)p;
    }
}

__global__ __launch_bounds__(256) void A2_k(const float* Mt, const float* S, const int* perm, float* A2) {
    __shared__ float Ms[4096];
    __shared__ float Ss[4096];
    __shared__ float T[64*KK];
    __shared__ int idxs[KK];
    int b = blockIdx.x, t = threadIdx.x;
    for (int i = t; i < 4096; i += 256) { Ms[i] = Mt[b*4096 + i]; Ss[i] = S[b*4096 + i]; }
    if (t < KK) idxs[t] = perm[b*KK + t] - b*64;
    __syncthreads();
    for (int i = t; i < 64*KK; i += 256) {
        int r = i / KK, j = i - r*KK;
        int cj = idxs[j];
        float acc = 0.0f;
        #pragma unroll
        for (int c = 0; c < 64; c++) acc += Ms[c*64 + r] * Ss[c*64 + cj];
        T[r*KK + j] = acc;
    }
    __syncthreads();
    for (int o = t; o < KK*KK; o += 256) {
        int i = o / KK, j = o - i*KK;
        float v;
        if (i == j) v = 1.0f;
        else {
            int ci = idxs[i];
            v = 0.0f;
            #pragma unroll
            for (int r = 0; r < 64; r++) v += Ss[r*64 + ci] * T[r*KK + j];
        }
        A2[(size_t)(b*KK + i) * NK + (size_t)(b*KK + j)] = v;
    }
}

// =======================================================================
extern "C" void kernel_launch(void* const* d_in, const int* in_sizes, int n_in,
                              void* d_out, int out_size) {
    const float* x   = (const float*)d_in[0];
    const int*   ei  = (const int*)d_in[1];
    const float* ewt = (const float*)d_in[2];
    const float* tx  = (const float*)d_in[3];
    const float* Wk  = (const float*)d_in[5];
    const float* W1  = (const float*)d_in[6];
    const float* W2  = (const float*)d_in[7];
    const float* W3  = (const float*)d_in[8];
    const float* lW  = (const float*)d_in[9];
    float* out = (float*)d_out;

    float* base = nullptr;
    cudaGetSymbolAddress((void**)&base, g_scratch);

    float* p_deg   = base + OFF_DEG;
    float* p_dinv  = base + OFF_DINV;
    float* p_M     = base + OFF_M;
    float* p_Cnt   = base + OFF_CNT;
    float* p_S     = base + OFF_S;
    float* p_xq    = base + OFF_XQ;
    float* p_agg   = base + OFF_AGG;
    float* p_xc    = base + OFF_XC;
    float* p_hcat  = base + OFF_HCAT;
    float* p_h1    = base + OFF_H1;
    float* p_h2    = base + OFF_H2;
    float* p_f1    = base + OFF_F1;
    float* p_f2    = base + OFF_F2;
    float* p_g1    = base + OFF_G1;
    float* p_g2    = base + OFF_G2;
    float* p_score = base + OFF_SCORE;
    int*   p_perm  = (int*)(base + OFF_PERM);

    // graph normalization + dense operators
    init_k<<<1024, 256>>>(p_deg, p_M, p_Cnt);
    deg_k<<<EE/256, 256>>>(ei, ewt, p_deg);
    dinv_k<<<NT/256, 256>>>(p_deg, p_dinv);
    scatter_k<<<ETOT/256, 256>>>(ei, ewt, p_dinv, p_M, p_Cnt);

    // x_q = hop(hop(x))
    hop2_k<<<dim3(BB, 2), 256>>>(p_M, x, p_xq);

    // batched attention pair: kv, weight base index (0 or 2), outputs
    auto attpair = [&](const float* kv, int wb, float* o0, float* o1) {
        gemm8_k<true,  false, true ><<<dim3(2, 64), 256>>>(
            kv, Wk + (size_t)wb*HH*HH, p_hcat, HH, HH, HH*HH, p_xq, tx);
        gemm8_k<false, true,  false><<<dim3(4, 64), 256>>>(
            p_hcat, W1 + (size_t)wb*4*HH*2*HH, p_h1, 4*HH, 2*HH, 4*HH*2*HH, nullptr, nullptr);
        gemm8_k<false, true,  false><<<dim3(2, 64), 256>>>(
            p_h1, W2 + (size_t)wb*2*HH*HH, p_h2, 2*HH, HH, 2*HH*HH, nullptr, nullptr);
        logsm_k<<<dim3(BB, 2), 64>>>(p_h2, W3 + (size_t)wb*HH, o0, o1);
    };

    attpair(x, 0, p_f1, p_f2);

    // edge softmax S and aggregation
    buildS_k<<<BB, 64>>>(p_f1, p_f2, p_Cnt, p_S);
    aggT_k<<<BB, 256>>>(p_S, x, p_agg);

    // x_c: both lin heads in one batched GEMM, then combine
    gemm8_k<true, false, false><<<dim3(2, 64), 256>>>(
        p_agg, lW, p_h2, HH, HH, HH*HH, nullptr, nullptr);
    xc_k<<<NT*HH/256, 256>>>(x, p_h2, p_xc);

    // x_q2 = hop(hop(x_c))
    hop2_k<<<dim3(BB, 2), 256>>>(p_M, p_xc, p_xq);

    attpair(p_xc, 2, p_g1, p_g2);

    // cluster score + top-k
    score_k<<<BB, 64>>>(p_g1, p_g2, p_score);
    topk_k<<<BB, 64>>>(p_score, p_perm);

    // outputs
    float* out_x    = out;
    float* out_A2   = out + (size_t)NK*HH;
    float* out_bat  = out + (size_t)NK*HH + (size_t)NK*NK;
    float* out_perm = out_bat + NK;

    xout_k<<<NK*HH/256, 256>>>(x, p_perm, p_score, out_x);
    meta_k<<<(NK + 255)/256, 256>>>(p_perm, out_bat, out_perm);
    cudaMemsetAsync(out_A2, 0, (size_t)NK*NK*sizeof(float));
    A2_k<<<BB, 256>>>(p_M, p_S, p_perm, out_A2);
}

// round 3
// speedup vs baseline: 2.1710x; 1.0727x over previous
#include <cuda_runtime.h>
#include <cuda_bf16.h>
#include <math.h>

// Problem constants
#define BB   64
#define NN   64
#define HH   128
#define NT   4096
#define EE   131072
#define ETOT 135168
#define KK   52
#define NK   3328
#define NEG  0.01f

// ---------------- scratch offsets (floats) ----------------
#define OFF_DEG    0
#define OFF_DINV   (OFF_DEG  + NT)
#define OFF_M      (OFF_DINV + NT)            // [b][c][r]
#define OFF_CNT    (OFF_M    + BB*NN*NN)      // [b][r][c]
#define OFF_S      (OFF_CNT  + BB*NN*NN)      // [b][r][c]
#define OFF_XQ     (OFF_S    + BB*NN*NN)
#define OFF_AGG    (OFF_XQ   + NT*HH)
#define OFF_XC     (OFF_AGG  + NT*HH)
#define OFF_HCAT   (OFF_XC   + NT*HH)         // 8192 x 384
#define OFF_H1     (OFF_HCAT + 8192*384)      // 8192 x 256
#define OFF_H2     (OFF_H1   + 8192*256)      // 8192 x 128
#define OFF_WF     (OFF_H2   + 8192*128)      // 4 x 384 x 256 folded W1
#define OFF_F1     (OFF_WF   + 4*384*256)
#define OFF_F2     (OFF_F1   + NT)
#define OFF_G1     (OFF_F2   + NT)
#define OFF_G2     (OFF_G1   + NT)
#define OFF_SCORE  (OFF_G2   + NT)
#define OFF_PERM   (OFF_SCORE+ NT)
#define SCRATCH_FLOATS (OFF_PERM + NK + 64)

__device__ float g_scratch[SCRATCH_FLOATS];

__device__ __forceinline__ float leaky(float v) { return v > 0.0f ? v : NEG * v; }

// ---- packed fp32 helpers (fma.rn.f32x2 — Blackwell 2x fp32 path) ----
__device__ __forceinline__ unsigned long long packf2(float f) {
    unsigned long long d; unsigned int u = __float_as_uint(f);
    asm("mov.b64 %0, {%1, %1};" : "=l"(d) : "r"(u));
    return d;
}
__device__ __forceinline__ void fma2(unsigned long long& acc,
                                     unsigned long long a, unsigned long long b) {
    asm("fma.rn.f32x2 %0, %1, %2, %0;" : "+l"(acc) : "l"(a), "l"(b));
}
__device__ __forceinline__ void unpackf2(unsigned long long v, float& lo, float& hi) {
    unsigned int ul, uh;
    asm("mov.b64 {%0, %1}, %2;" : "=r"(ul), "=r"(uh) : "l"(v));
    lo = __uint_as_float(ul); hi = __uint_as_float(uh);
}

// ---------------- init ----------------
__global__ void init_k(float* deg, float* M, float* Cnt) {
    int i  = blockIdx.x * blockDim.x + threadIdx.x;
    int st = gridDim.x * blockDim.x;
    for (int j = i; j < BB*NN*NN; j += st) { M[j] = 0.0f; Cnt[j] = 0.0f; }
    for (int j = i; j < NT; j += st) deg[j] = 1.0f;
}

__global__ void deg_k(const int* ei, const float* ew, float* deg) {
    int e = blockIdx.x * blockDim.x + threadIdx.x;
    if (e < EE) atomicAdd(&deg[ei[EE + e]], ew[e]);
}

__global__ void dinv_k(const float* deg, float* dinv) {
    int i = blockIdx.x * blockDim.x + threadIdx.x;
    if (i < NT) {
        float d = deg[i];
        dinv[i] = d > 0.0f ? (1.0f / sqrtf(fmaxf(d, 1e-12f))) : 0.0f;
    }
}

__global__ void scatter_k(const int* ei, const float* ewt,
                          const float* dinv, float* M, float* Cnt) {
    int t = blockIdx.x * blockDim.x + threadIdx.x;
    if (t >= ETOT) return;
    int r, c; float w;
    if (t < EE) { r = ei[t]; c = ei[EE + t]; w = ewt[t]; }
    else        { r = t - EE; c = r; w = 1.0f; }
    int b  = r >> 6;
    int rl = r & 63, cl = c & 63;
    float e = dinv[r] * w * dinv[c];
    atomicAdd(&M[b*4096 + cl*64 + rl], e);       // M[c][r] = A_d[r][c]
    atomicAdd(&Cnt[b*4096 + rl*64 + cl], 1.0f);
}

// ---------------- fold W1: Wf = [W1_0+W1_2 ; W1_1-W1_2 ; W1_3] --------------
__global__ void fold_k(const float* __restrict__ W1, float* __restrict__ Wf) {
    int i = blockIdx.x * 256 + threadIdx.x;        // 4*384*256
    if (i >= 4*384*256) return;
    int w = i / (384*256);
    int rem = i - w*(384*256);
    int r = rem >> 8, c = rem & 255;
    const float* base = W1 + (size_t)w * 512 * 256;
    float v;
    if (r < 128)      v = base[r*256 + c] + base[(r+256)*256 + c];
    else if (r < 256) v = base[r*256 + c] - base[(r+128)*256 + c];
    else              v = base[(r+128)*256 + c];
    Wf[i] = v;
}

// ---------------- fused two-hop: out = M @ (M @ in) per batch --------------
__global__ __launch_bounds__(256) void hop2_k(const float* Mt, const float* in, float* out) {
    __shared__ float Ms[4096];
    __shared__ float Xs[64*64];
    int b = blockIdx.x, hb = blockIdx.y * 64, t = threadIdx.x;
    for (int i = t; i < 4096; i += 256) Ms[i] = Mt[b*4096 + i];
    for (int i = t; i < 4096; i += 256) {
        int r = i >> 6, h = i & 63;
        Xs[i] = in[b*8192 + r*128 + hb + h];
    }
    __syncthreads();
    float reg[16];
    #pragma unroll
    for (int s = 0; s < 16; s++) {
        int i = t + 256*s;
        int c = i >> 6, h = i & 63;
        float acc = 0.0f;
        #pragma unroll
        for (int r = 0; r < 64; r++) acc += Ms[c*64 + r] * Xs[r*64 + h];
        reg[s] = acc;
    }
    __syncthreads();
    #pragma unroll
    for (int s = 0; s < 16; s++) Xs[t + 256*s] = reg[s];
    __syncthreads();
    #pragma unroll
    for (int s = 0; s < 16; s++) {
        int i = t + 256*s;
        int c = i >> 6, h = i & 63;
        float acc = 0.0f;
        #pragma unroll
        for (int r = 0; r < 64; r++) acc += Ms[c*64 + r] * Xs[r*64 + h];
        out[b*8192 + c*128 + hb + h] = acc;
    }
}

// ---------------- agg = S^T x per batch ----------------
__global__ __launch_bounds__(256) void aggT_k(const float* St, const float* in, float* out) {
    __shared__ float Ms[4096];
    __shared__ float Xs[8192];
    int b = blockIdx.x, t = threadIdx.x;
    for (int i = t; i < 4096; i += 256) Ms[i] = St[b*4096 + i];
    for (int i = t; i < 8192; i += 256) Xs[i] = in[b*8192 + i];
    __syncthreads();
    for (int i = t; i < 8192; i += 256) {
        int c = i >> 7, h = i & 127;
        float acc = 0.0f;
        #pragma unroll
        for (int r = 0; r < 64; r++) acc += Ms[r*64 + c] * Xs[r*128 + h];
        out[b*8192 + i] = acc;
    }
}

// ---------------- f32x2 double-buffered GEMM -------------------------------
// C[(rows) x Nn] = act(A @ (W + half*Wstride)), half = rowBase>>12
// BN=128, BK=8, TN=8 fixed; BM/TM template. 256 threads.
// EPI: 0 = plain store, 1 = leaky store, 2 = hcat3 epilogue (C stride 384:
//      [a, q, a*q], q from q0 rows<4096 else txg per-batch).
template<int BM, int TM, bool AWRAP, int EPI>
__global__ __launch_bounds__(256) void gemmx_k(
    const float* __restrict__ A, const float* __restrict__ W,
    float* __restrict__ C, int K, int Nn, int Wstride,
    const float* __restrict__ q0, const float* __restrict__ txg)
{
    constexpr int BK = 8;
    __shared__ float As[2][BK][BM + 4];
    __shared__ float Ws[2][BK][128];
    int tid = threadIdx.x;
    int rowBase = blockIdx.y * BM;
    int colBase = blockIdx.x * 128;
    const float* Wp = W + (size_t)(rowBase >> 12) * Wstride;

    int am = tid >> 1, akq = (tid & 1) * 4;       // A loader coords
    int wk = tid >> 5, wn = (tid & 31) * 4;       // W loader coords
    bool aActive = (BM == 128) || (tid < 128);

    int ty = tid >> 4, tx = tid & 15;

    unsigned long long acc2[TM][4];
    #pragma unroll
    for (int i = 0; i < TM; i++)
        #pragma unroll
        for (int j = 0; j < 4; j++) acc2[i][j] = 0ull;

    // prologue: stage 0
    float4 ra, rw;
    if (aActive) {
        int arow = rowBase + am; if (AWRAP) arow &= 4095;
        ra = *(const float4*)&A[(size_t)arow * K + akq];
    }
    rw = *(const float4*)&Wp[(size_t)wk * Nn + colBase + wn];
    if (aActive) {
        As[0][akq+0][am] = ra.x; As[0][akq+1][am] = ra.y;
        As[0][akq+2][am] = ra.z; As[0][akq+3][am] = ra.w;
    }
    *(float4*)&Ws[0][wk][wn] = rw;
    __syncthreads();

    int s = 0;
    int nIter = K >> 3;
    for (int it = 0; it < nIter; it++) {
        bool more = (it + 1) < nIter;
        if (more) {
            int k0 = (it + 1) * BK;
            if (aActive) {
                int arow = rowBase + am; if (AWRAP) arow &= 4095;
                ra = *(const float4*)&A[(size_t)arow * K + k0 + akq];
            }
            rw = *(const float4*)&Wp[(size_t)(k0 + wk) * Nn + colBase + wn];
        }
        // compute on stage s
        #pragma unroll
        for (int kk = 0; kk < BK; kk++) {
            float av[TM];
            {
                const float4 v0 = *(const float4*)&As[s][kk][ty*TM];
                av[0] = v0.x; av[1] = v0.y; av[2] = v0.z; av[3] = v0.w;
                if (TM == 8) {
                    const float4 v1 = *(const float4*)&As[s][kk][ty*TM + 4];
                    av[4] = v1.x; av[5] = v1.y; av[6] = v1.z; av[7] = v1.w;
                }
            }
            const ulonglong2 bp0 = *(const ulonglong2*)&Ws[s][kk][tx*8];
            const ulonglong2 bp1 = *(const ulonglong2*)&Ws[s][kk][tx*8 + 4];
            unsigned long long b2[4] = { bp0.x, bp0.y, bp1.x, bp1.y };
            #pragma unroll
            for (int i = 0; i < TM; i++) {
                unsigned long long a2 = packf2(av[i]);
                #pragma unroll
                for (int j = 0; j < 4; j++) fma2(acc2[i][j], a2, b2[j]);
            }
        }
        if (more) {
            int ns = s ^ 1;
            if (aActive) {
                As[ns][akq+0][am] = ra.x; As[ns][akq+1][am] = ra.y;
                As[ns][akq+2][am] = ra.z; As[ns][akq+3][am] = ra.w;
            }
            *(float4*)&Ws[ns][wk][wn] = rw;
            __syncthreads();
            s = ns;
        }
    }

    // epilogue
    #pragma unroll
    for (int i = 0; i < TM; i++) {
        int row = rowBase + ty*TM + i;
        #pragma unroll
        for (int j = 0; j < 4; j++) {
            float lo, hi;
            unpackf2(acc2[i][j], lo, hi);
            int col = colBase + tx*8 + 2*j;
            if (EPI == 2) {
                float q0v, q1v;
                if (row < 4096) {
                    q0v = q0[(row << 7) + col];
                    q1v = q0[(row << 7) + col + 1];
                } else {
                    int nb = ((row - 4096) >> 6) << 7;
                    q0v = txg[nb + col];
                    q1v = txg[nb + col + 1];
                }
                float* o = C + (size_t)row * 384 + col;
                o[0]   = lo;        o[1]   = hi;
                o[128] = q0v;       o[129] = q1v;
                o[256] = lo * q0v;  o[257] = hi * q1v;
            } else {
                if (EPI == 1) { lo = leaky(lo); hi = leaky(hi); }
                float* o = C + (size_t)row * Nn + col;
                o[0] = lo; o[1] = hi;
            }
        }
    }
}

// ---------------- fused logit + per-batch softmax --------------------------
__global__ void logsm_k(const float* __restrict__ h2, const float* __restrict__ W3,
                        float* out0, float* out1) {
    __shared__ float sh[64];
    int b = blockIdx.x, half = blockIdx.y, t = threadIdx.x;
    int row = half*4096 + b*64 + t;
    const float4* hp = (const float4*)(h2 + (size_t)row * 128);
    const float4* wp = (const float4*)(W3 + half * 128);
    float s = 0.0f;
    #pragma unroll
    for (int i = 0; i < 32; i++) {
        float4 hv = hp[i], wv = wp[i];
        s += hv.x*wv.x + hv.y*wv.y + hv.z*wv.z + hv.w*wv.w;
    }
    float v = leaky(s);
    sh[t] = v; __syncthreads();
    for (int o = 32; o; o >>= 1) { if (t < o) sh[t] = fmaxf(sh[t], sh[t+o]); __syncthreads(); }
    float m = sh[0]; __syncthreads();
    float e = expf(v - m);
    sh[t] = e; __syncthreads();
    for (int o = 32; o; o >>= 1) { if (t < o) sh[t] += sh[t+o]; __syncthreads(); }
    (half ? out1 : out0)[b*64 + t] = e / sh[0];
}

// ---------------- build S ----------------
__global__ void buildS_k(const float* f1, const float* f2, const float* Cnt, float* S) {
    __shared__ float Cs[4096], f1s[64], f2s[64];
    int b = blockIdx.x, t = threadIdx.x;
    f1s[t] = f1[b*64 + t];
    f2s[t] = f2[b*64 + t];
    for (int i = t; i < 4096; i += 64) Cs[i] = Cnt[b*4096 + i];
    __syncthreads();
    int c = t;
    float m = -3.0e38f;
    for (int r = 0; r < 64; r++)
        if (Cs[r*64 + c] > 0.0f) m = fmaxf(m, leaky(f1s[c] + f2s[r]));
    float d = 0.0f;
    for (int r = 0; r < 64; r++) {
        float cnt = Cs[r*64 + c];
        if (cnt > 0.0f) d += cnt * expf(leaky(f1s[c] + f2s[r]) - m);
    }
    for (int r = 0; r < 64; r++) {
        float cnt = Cs[r*64 + c];
        float v = 0.0f;
        if (cnt > 0.0f) v = cnt * expf(leaky(f1s[c] + f2s[r]) - m) / d;
        S[b*4096 + r*64 + c] = v;
    }
}

// ---------------- x_c from two lin heads ----------------
__global__ void xc_k(const float* x, const float* t2, float* xc) {
    int i = blockIdx.x * blockDim.x + threadIdx.x;
    float l0 = leaky(x[i] + t2[i]);
    float l1 = leaky(x[i] + t2[i + NT*HH]);
    xc[i] = 0.5f * (l0 + l1);
}

// ---------------- fused score softmax + per-batch top-52 -------------------
__global__ void scoretopk_k(const float* g1, const float* g2, float* score, int* perm) {
    __shared__ float sh[64];
    __shared__ float sv[64];
    __shared__ float rv[64];
    __shared__ int   ri[64];
    int b = blockIdx.x, t = threadIdx.x;
    float v = g1[b*64 + t] + g2[b*64 + t];
    sh[t] = v; __syncthreads();
    for (int o = 32; o; o >>= 1) { if (t < o) sh[t] = fmaxf(sh[t], sh[t+o]); __syncthreads(); }
    float m = sh[0]; __syncthreads();
    float e = expf(v - m);
    sh[t] = e; __syncthreads();
    for (int o = 32; o; o >>= 1) { if (t < o) sh[t] += sh[t+o]; __syncthreads(); }
    float sc = e / sh[0];
    score[b*64 + t] = sc;
    sv[t] = sc;
    __syncthreads();
    for (int j = 0; j < KK; j++) {
        rv[t] = sv[t]; ri[t] = t;
        __syncthreads();
        for (int o = 32; o; o >>= 1) {
            if (t < o) {
                if (rv[t+o] > rv[t] || (rv[t+o] == rv[t] && ri[t+o] < ri[t])) {
                    rv[t] = rv[t+o]; ri[t] = ri[t+o];
                }
            }
            __syncthreads();
        }
        if (t == 0) { perm[b*KK + j] = b*64 + ri[0]; sv[ri[0]] = -3.0e38f; }
        __syncthreads();
    }
}

// ---------------- outputs: x_out + batch_out + perm ----------------
__global__ void xout_k(const float* x, const int* perm, const float* score,
                       float* out, float* bout, float* pout) {
    int i = blockIdx.x * blockDim.x + threadIdx.x;
    int e = i >> 7;
    int p = perm[e];
    out[i] = x[(size_t)p * 128 + (i & 127)] * score[p];
    if ((i & 127) == 0) {
        bout[e] = (float)(p >> 6);
        pout[e] = (float)p;
    }
}

__global__ __launch_bounds__(256) void A2_k(const float* Mt, const float* S, const int* perm, float* A2) {
    __shared__ float Ms[4096];
    __shared__ float Ss[4096];
    __shared__ float T[64*KK];
    __shared__ int idxs[KK];
    int b = blockIdx.x, t = threadIdx.x;
    for (int i = t; i < 4096; i += 256) { Ms[i] = Mt[b*4096 + i]; Ss[i] = S[b*4096 + i]; }
    if (t < KK) idxs[t] = perm[b*KK + t] - b*64;
    __syncthreads();
    for (int i = t; i < 64*KK; i += 256) {
        int r = i / KK, j = i - r*KK;
        int cj = idxs[j];
        float acc = 0.0f;
        #pragma unroll
        for (int c = 0; c < 64; c++) acc += Ms[c*64 + r] * Ss[c*64 + cj];
        T[r*KK + j] = acc;
    }
    __syncthreads();
    for (int o = t; o < KK*KK; o += 256) {
        int i = o / KK, j = o - i*KK;
        float v;
        if (i == j) v = 1.0f;
        else {
            int ci = idxs[i];
            v = 0.0f;
            #pragma unroll
            for (int r = 0; r < 64; r++) v += Ss[r*64 + ci] * T[r*KK + j];
        }
        A2[(size_t)(b*KK + i) * NK + (size_t)(b*KK + j)] = v;
    }
}

// =======================================================================
extern "C" void kernel_launch(void* const* d_in, const int* in_sizes, int n_in,
                              void* d_out, int out_size) {
    const float* x   = (const float*)d_in[0];
    const int*   ei  = (const int*)d_in[1];
    const float* ewt = (const float*)d_in[2];
    const float* tx  = (const float*)d_in[3];
    const float* Wk  = (const float*)d_in[5];
    const float* W1  = (const float*)d_in[6];
    const float* W2  = (const float*)d_in[7];
    const float* W3  = (const float*)d_in[8];
    const float* lW  = (const float*)d_in[9];
    float* out = (float*)d_out;

    float* base = nullptr;
    cudaGetSymbolAddress((void**)&base, g_scratch);

    float* p_deg   = base + OFF_DEG;
    float* p_dinv  = base + OFF_DINV;
    float* p_M     = base + OFF_M;
    float* p_Cnt   = base + OFF_CNT;
    float* p_S     = base + OFF_S;
    float* p_xq    = base + OFF_XQ;
    float* p_agg   = base + OFF_AGG;
    float* p_xc    = base + OFF_XC;
    float* p_hcat  = base + OFF_HCAT;
    float* p_h1    = base + OFF_H1;
    float* p_h2    = base + OFF_H2;
    float* p_wf    = base + OFF_WF;
    float* p_f1    = base + OFF_F1;
    float* p_f2    = base + OFF_F2;
    float* p_g1    = base + OFF_G1;
    float* p_g2    = base + OFF_G2;
    float* p_score = base + OFF_SCORE;
    int*   p_perm  = (int*)(base + OFF_PERM);

    // weight fold (independent of graph work)
    fold_k<<<(4*384*256 + 255)/256, 256>>>(W1, p_wf);

    // graph normalization + dense operators
    init_k<<<1024, 256>>>(p_deg, p_M, p_Cnt);
    deg_k<<<EE/256, 256>>>(ei, ewt, p_deg);
    dinv_k<<<NT/256, 256>>>(p_deg, p_dinv);
    scatter_k<<<ETOT/256, 256>>>(ei, ewt, p_dinv, p_M, p_Cnt);

    // x_q = hop(hop(x))
    hop2_k<<<dim3(BB, 2), 256>>>(p_M, x, p_xq);

    // batched attention pair: kv, weight base index (0 or 2), outputs
    auto attpair = [&](const float* kv, int wb, float* o0, float* o1) {
        // a = kv @ Wk  -> hcat3 [a, q, a*q]
        gemmx_k<64, 4, true, 2><<<dim3(1, 128), 256>>>(
            kv, Wk + (size_t)wb*HH*HH, p_hcat, HH, HH, HH*HH, p_xq, tx);
        // h1 = leaky(hcat3 @ Wf)
        gemmx_k<128, 8, false, 1><<<dim3(2, 64), 256>>>(
            p_hcat, p_wf + (size_t)wb*384*256, p_h1, 384, 2*HH, 384*256, nullptr, nullptr);
        // h2 = leaky(h1 @ W2)
        gemmx_k<64, 4, false, 1><<<dim3(1, 128), 256>>>(
            p_h1, W2 + (size_t)wb*2*HH*HH, p_h2, 2*HH, HH, 2*HH*HH, nullptr, nullptr);
        logsm_k<<<dim3(BB, 2), 64>>>(p_h2, W3 + (size_t)wb*HH, o0, o1);
    };

    attpair(x, 0, p_f1, p_f2);

    // edge softmax S and aggregation
    buildS_k<<<BB, 64>>>(p_f1, p_f2, p_Cnt, p_S);
    aggT_k<<<BB, 256>>>(p_S, x, p_agg);

    // x_c: both lin heads in one batched GEMM, then combine
    gemmx_k<64, 4, true, 0><<<dim3(1, 128), 256>>>(
        p_agg, lW, p_h2, HH, HH, HH*HH, nullptr, nullptr);
    xc_k<<<NT*HH/256, 256>>>(x, p_h2, p_xc);

    // x_q2 = hop(hop(x_c))
    hop2_k<<<dim3(BB, 2), 256>>>(p_M, p_xc, p_xq);

    attpair(p_xc, 2, p_g1, p_g2);

    // cluster score + top-k (fused)
    scoretopk_k<<<BB, 64>>>(p_g1, p_g2, p_score, p_perm);

    // outputs
    float* out_x    = out;
    float* out_A2   = out + (size_t)NK*HH;
    float* out_bat  = out + (size_t)NK*HH + (size_t)NK*NK;
    float* out_perm = out_bat + NK;

    xout_k<<<NK*HH/256, 256>>>(x, p_perm, p_score, out_x, out_bat, out_perm);
    cudaMemsetAsync(out_A2, 0, (size_t)NK*NK*sizeof(float));
    A2_k<<<BB, 256>>>(p_M, p_S, p_perm, out_A2);
}

// round 5
// speedup vs baseline: 4.2084x; 1.9385x over previous
#include <cuda_runtime.h>
#include <cstdint>
#include <math.h>

#define BB   64
#define HH   128
#define NT   4096
#define EE   131072
#define KK   52
#define NK   3328
#define NEG  0.01f

// Only global scratch: folded W1 weights (4 heads x 384 x 256)
__device__ float g_wf[4*384*256];

// ---------------- shared memory layout (float offsets) ----------------
#define SM_M    0          // 4096  M[c*64+r] = A_d[r][c]
#define SM_S    4096       // 4096  S[r*64+c]
#define SM_X    8192       // 8192  x (64x128)
#define SM_Q    16384      // 8192  q (xq / qt / xq2)
#define SM_AXC  24576      // 8192  a(att1) -> h2 -> xc -> h2(att2)
#define SM_H1   32768      // 16384 h1 (64x256); also a(att2)@+0, apq@+8192, tmp/agg@+0, T@+0
#define SM_MISC 49152
#define MS_DEG   0
#define MS_DINV  64
#define MS_FOWN  128
#define MS_FPEER 192
#define MS_GOWN  256
#define MS_GPEER 320
#define MS_SCORE 384
#define MS_RED   448       // 256
#define MS_PERM  704       // 64 ints
#define MS_CNT   768       // 2048 ints (packed 2x uint16)
#define SM_TOTALF (SM_MISC + 768 + 2048)
#define SM_BYTES  (SM_TOTALF * 4)

__device__ __forceinline__ float leaky(float v) { return v > 0.0f ? v : NEG * v; }

// ---- packed fp32 (fma.rn.f32x2) ----
__device__ __forceinline__ unsigned long long packf2(float f) {
    unsigned long long d; unsigned int u = __float_as_uint(f);
    asm("mov.b64 %0, {%1, %1};" : "=l"(d) : "r"(u));
    return d;
}
__device__ __forceinline__ void fma2(unsigned long long& acc,
                                     unsigned long long a, unsigned long long b) {
    asm("fma.rn.f32x2 %0, %1, %2, %0;" : "+l"(acc) : "l"(a), "l"(b));
}
__device__ __forceinline__ void unpackf2(unsigned long long v, float& lo, float& hi) {
    unsigned int ul, uh;
    asm("mov.b64 {%0, %1}, %2;" : "=r"(ul), "=r"(uh) : "l"(v));
    lo = __uint_as_float(ul); hi = __uint_as_float(uh);
}

// ---- cluster helpers ----
__device__ __forceinline__ void cluster_sync() {
    asm volatile("barrier.cluster.arrive.aligned;" ::: "memory");
    asm volatile("barrier.cluster.wait.aligned;" ::: "memory");
}
__device__ __forceinline__ float dsread(const float* p, unsigned peer) {
    unsigned addr = (unsigned)__cvta_generic_to_shared((void*)p);
    unsigned ra; float v;
    asm volatile("mapa.shared::cluster.u32 %0, %1, %2;" : "=r"(ra) : "r"(addr), "r"(peer));
    asm volatile("ld.shared::cluster.f32 %0, [%1];" : "=f"(v) : "r"(ra));
    return v;
}

// ---- GEMM microkernel: C[64 x N], thread tile 8 rows x (2*JN) cols --------
// A in smem (float4 along k), W row-major (global or smem), f32x2 accum.
template<int JN>
__device__ __forceinline__ void gseg(const float* __restrict__ As, int ldA,
                                     const float* __restrict__ W, int wld, int K,
                                     int ty, int txc, unsigned long long acc[8][JN]) {
    const float* a0 = As + ty * 8 * ldA;
    const float* wbase = W + txc * (2 * JN);
    for (int k = 0; k < K; k += 4) {
        float4 av[8];
        #pragma unroll
        for (int r = 0; r < 8; r++) av[r] = *(const float4*)(a0 + r * ldA + k);
        #pragma unroll
        for (int kk = 0; kk < 4; kk++) {
            const ulonglong2* wp = (const ulonglong2*)(wbase + (size_t)(k + kk) * wld);
            unsigned long long b2[JN];
            { ulonglong2 p0 = wp[0]; b2[0] = p0.x; b2[1] = p0.y; }
            if (JN == 4) { ulonglong2 p1 = wp[1]; b2[2] = p1.x; b2[3] = p1.y; }
            #pragma unroll
            for (int r = 0; r < 8; r++) {
                float aval = kk == 0 ? av[r].x : kk == 1 ? av[r].y : kk == 2 ? av[r].z : av[r].w;
                unsigned long long a2 = packf2(aval);
                #pragma unroll
                for (int j = 0; j < JN; j++) fma2(acc[r][j], a2, b2[j]);
            }
        }
    }
}

// Transposed-A variant for agg: A[c][k] = S[k*64+c] (scalar, warp-broadcast)
template<int JN>
__device__ __forceinline__ void gsegT(const float* __restrict__ S,
                                      const float* __restrict__ W, int wld, int K,
                                      int ty, int txc, unsigned long long acc[8][JN]) {
    int c0 = ty * 8;
    const float* wbase = W + txc * (2 * JN);
    for (int k = 0; k < K; k++) {
        const ulonglong2* wp = (const ulonglong2*)(wbase + (size_t)k * wld);
        unsigned long long b2[JN];
        { ulonglong2 p0 = wp[0]; b2[0] = p0.x; b2[1] = p0.y; }
        if (JN == 4) { ulonglong2 p1 = wp[1]; b2[2] = p1.x; b2[3] = p1.y; }
        #pragma unroll
        for (int r = 0; r < 8; r++) {
            unsigned long long a2 = packf2(S[k * 64 + c0 + r]);
            #pragma unroll
            for (int j = 0; j < JN; j++) fma2(acc[r][j], a2, b2[j]);
        }
    }
}

template<int JN, int ACT>
__device__ __forceinline__ void estore(float* C, int ldC, int ty, int txc,
                                       unsigned long long acc[8][JN]) {
    #pragma unroll
    for (int r = 0; r < 8; r++) {
        float* crow = C + (ty * 8 + r) * ldC + txc * (2 * JN);
        #pragma unroll
        for (int j = 0; j < JN; j++) {
            float lo, hi; unpackf2(acc[r][j], lo, hi);
            if (ACT == 1) { lo = leaky(lo); hi = leaky(hi); }
            ((float2*)crow)[j] = make_float2(lo, hi);
        }
    }
}

// ---- in-place softmax over v[0..63]; red = 256-float scratch; all 256 threads
__device__ void softmax64(float* v, float* red, int t) {
    if (t < 64) red[t] = v[t];
    __syncthreads();
    for (int o = 32; o; o >>= 1) { if (t < o) red[t] = fmaxf(red[t], red[t + o]); __syncthreads(); }
    float m = red[0];
    __syncthreads();
    if (t < 64) { float e = expf(v[t] - m); v[t] = e; red[t] = e; }
    __syncthreads();
    for (int o = 32; o; o >>= 1) { if (t < o) red[t] += red[t + o]; __syncthreads(); }
    float d = red[0];
    __syncthreads();
    if (t < 64) v[t] = v[t] / d;
    __syncthreads();
}

// ---- full attention branch: fout = segsoftmax(leaky(MLP(kv, q))) ----------
__device__ void attention(float* sm, int t, int ty, int txc,
                          const float* kv, const float* q, float* aDest,
                          int head, const float* Wk, const float* W2, const float* W3,
                          float* fout) {
    float* red = sm + SM_MISC + MS_RED;
    float* apq = sm + SM_H1 + 8192;
    float* h1  = sm + SM_H1;
    float* h2  = sm + SM_AXC;

    // a = kv @ Wk[head]
    {
        unsigned long long acc[8][2];
        #pragma unroll
        for (int r = 0; r < 8; r++) { acc[r][0] = 0ull; acc[r][1] = 0ull; }
        gseg<2>(kv, 128, Wk + head * 16384, 128, 128, ty, txc, acc);
        estore<2, 0>(aDest, 128, ty, txc, acc);
    }
    __syncthreads();
    // apq = a * q
    for (int i = t * 4; i < 8192; i += 1024) {
        float4 av = *(const float4*)(aDest + i);
        float4 qv = *(const float4*)(q + i);
        *(float4*)(apq + i) = make_float4(av.x * qv.x, av.y * qv.y, av.z * qv.z, av.w * qv.w);
    }
    __syncthreads();
    // h1 = leaky([a,q,a*q] @ Wf[head])  (folded K=384)
    {
        unsigned long long acc[8][4];
        #pragma unroll
        for (int r = 0; r < 8; r++)
            #pragma unroll
            for (int j = 0; j < 4; j++) acc[r][j] = 0ull;
        const float* Wf = g_wf + (size_t)head * 384 * 256;
        gseg<4>(aDest, 128, Wf,             256, 128, ty, txc, acc);
        gseg<4>(q,     128, Wf + 128 * 256, 256, 128, ty, txc, acc);
        gseg<4>(apq,   128, Wf + 256 * 256, 256, 128, ty, txc, acc);
        __syncthreads();                 // a/apq reads done before h1 overwrite
        estore<4, 1>(h1, 256, ty, txc, acc);
    }
    __syncthreads();
    // h2 = leaky(h1 @ W2[head])
    {
        unsigned long long acc[8][2];
        #pragma unroll
        for (int r = 0; r < 8; r++) { acc[r][0] = 0ull; acc[r][1] = 0ull; }
        gseg<2>(h1, 256, W2 + head * 32768, 128, 256, ty, txc, acc);
        estore<2, 1>(h2, 128, ty, txc, acc);
    }
    __syncthreads();
    // logit = leaky(h2 @ W3[head]); softmax over 64
    {
        int row = t >> 2, part = t & 3;
        const float4* hp = (const float4*)(h2 + row * 128 + part * 32);
        const float4* wp = (const float4*)(W3 + head * 128 + part * 32);
        float s = 0.0f;
        #pragma unroll
        for (int i = 0; i < 8; i++) {
            float4 a = hp[i], b = wp[i];
            s += a.x * b.x + a.y * b.y + a.z * b.z + a.w * b.w;
        }
        red[t] = s;
    }
    __syncthreads();
    if (t < 64) fout[t] = leaky(red[t * 4] + red[t * 4 + 1] + red[t * 4 + 2] + red[t * 4 + 3]);
    __syncthreads();
    softmax64(fout, red, t);
}

// ---------------- fold W1 ----------------
__global__ void fold_k(const float* __restrict__ W1) {
    int i = blockIdx.x * 256 + threadIdx.x;
    if (i >= 4 * 384 * 256) return;
    int w = i / (384 * 256);
    int rem = i - w * (384 * 256);
    int r = rem >> 8, c = rem & 255;
    const float* base = W1 + (size_t)w * 512 * 256;
    float v;
    if (r < 128)      v = base[r * 256 + c] + base[(r + 256) * 256 + c];
    else if (r < 256) v = base[r * 256 + c] - base[(r + 128) * 256 + c];
    else              v = base[(r + 128) * 256 + c];
    g_wf[i] = v;
}

// ---------------- THE mega kernel: one cluster = one batch -----------------
extern __shared__ float sm[];

__global__ void __launch_bounds__(256, 1) __cluster_dims__(2, 1, 1)
mega_k(const float* __restrict__ xg, const int* __restrict__ ei,
       const float* __restrict__ ew, const float* __restrict__ tx,
       const float* __restrict__ Wk, const float* __restrict__ W2,
       const float* __restrict__ W3, const float* __restrict__ lW,
       float* __restrict__ outx, float* __restrict__ outA2,
       float* __restrict__ outb, float* __restrict__ outp) {
    int t = threadIdx.x;
    int ty = t >> 5, txc = t & 31;
    int b = blockIdx.x >> 1;
    unsigned rank = blockIdx.x & 1;

    float* Ms    = sm + SM_M;
    float* Ss    = sm + SM_S;
    float* xs    = sm + SM_X;
    float* qs    = sm + SM_Q;
    float* axc   = sm + SM_AXC;
    float* h1b   = sm + SM_H1;
    float* degs  = sm + SM_MISC + MS_DEG;
    float* dinvs = sm + SM_MISC + MS_DINV;
    float* fown  = sm + SM_MISC + MS_FOWN;
    float* fpeer = sm + SM_MISC + MS_FPEER;
    float* gown  = sm + SM_MISC + MS_GOWN;
    float* gpeer = sm + SM_MISC + MS_GPEER;
    float* sscore= sm + SM_MISC + MS_SCORE;
    float* red   = sm + SM_MISC + MS_RED;
    int*   permsh= (int*)(sm + SM_MISC + MS_PERM);
    int*   cw    = (int*)(sm + SM_MISC + MS_CNT);

    // ---- stage 0: load x, init, build deg/dinv/M/Cnt ----
    for (int i = t; i < 4096; i += 256) Ms[i] = 0.0f;
    for (int i = t; i < 2048; i += 256) cw[i] = 0;
    if (t < 64) degs[t] = 1.0f;     // self-loop weight
    for (int i = t * 4; i < 8192; i += 1024)
        *(float4*)(xs + i) = *(const float4*)(xg + (size_t)b * 8192 + i);
    __syncthreads();

    int er[8], ec[8]; float ewv[8];
    #pragma unroll
    for (int u = 0; u < 8; u++) {
        int e = b * 2048 + t + u * 256;
        er[u] = ei[e] - b * 64;
        ec[u] = ei[EE + e] - b * 64;
        ewv[u] = ew[e];
        atomicAdd(&degs[ec[u]], ewv[u]);
    }
    __syncthreads();
    if (t < 64) {
        float d = degs[t];
        dinvs[t] = d > 0.0f ? (1.0f / sqrtf(fmaxf(d, 1e-12f))) : 0.0f;
    }
    __syncthreads();
    #pragma unroll
    for (int u = 0; u < 8; u++) {
        atomicAdd(&Ms[ec[u] * 64 + er[u]], dinvs[er[u]] * ewv[u] * dinvs[ec[u]]);
        atomicAdd(&cw[(er[u] * 64 + ec[u]) >> 1], 1 << ((ec[u] & 1) * 16));
    }
    if (t < 64) {
        float dv = dinvs[t];
        atomicAdd(&Ms[t * 64 + t], dv * dv);
        atomicAdd(&cw[(t * 64 + t) >> 1], 1 << ((t & 1) * 16));
    }
    __syncthreads();

    // ---- stage 1: q = hop2(x) for rank0, q = broadcast target for rank1 ----
    if (rank == 0) {
        float* tmp = h1b;
        unsigned long long acc[8][2];
        #pragma unroll
        for (int r = 0; r < 8; r++) { acc[r][0] = 0ull; acc[r][1] = 0ull; }
        gseg<2>(Ms, 64, xs, 128, 64, ty, txc, acc);
        estore<2, 0>(tmp, 128, ty, txc, acc);
        __syncthreads();
        unsigned long long acc2[8][2];
        #pragma unroll
        for (int r = 0; r < 8; r++) { acc2[r][0] = 0ull; acc2[r][1] = 0ull; }
        gseg<2>(Ms, 64, tmp, 128, 64, ty, txc, acc2);
        estore<2, 0>(qs, 128, ty, txc, acc2);
    } else {
        for (int i = t * 4; i < 8192; i += 1024)
            *(float4*)(qs + i) = *(const float4*)(tx + b * 128 + (i & 127));
    }
    __syncthreads();

    // ---- stage 2: attention #1 (head = rank) -> fown ----
    attention(sm, t, ty, txc, xs, qs, axc, (int)rank, Wk, W2, W3, fown);

    // exchange f with peer CTA
    cluster_sync();
    if (t < 64) fpeer[t] = dsread(fown + t, rank ^ 1);
    __syncthreads();

    // ---- stage 3: build S (edge softmax, count-weighted) ----
    {
        const float* f1 = rank ? fpeer : fown;
        const float* f2 = rank ? fown : fpeer;
        int c = t >> 2, rq = t & 3;
        float f1c = f1[c];
        float mx = -3.0e38f;
        for (int r = rq * 16; r < rq * 16 + 16; r++) {
            int cnt = (cw[(r * 64 + c) >> 1] >> ((c & 1) * 16)) & 0xffff;
            if (cnt) mx = fmaxf(mx, leaky(f1c + f2[r]));
        }
        red[t] = mx; __syncthreads();
        mx = fmaxf(fmaxf(red[c * 4], red[c * 4 + 1]), fmaxf(red[c * 4 + 2], red[c * 4 + 3]));
        __syncthreads();
        float dp = 0.0f;
        for (int r = rq * 16; r < rq * 16 + 16; r++) {
            int cnt = (cw[(r * 64 + c) >> 1] >> ((c & 1) * 16)) & 0xffff;
            float e = 0.0f;
            if (cnt) e = (float)cnt * expf(leaky(f1c + f2[r]) - mx);
            Ss[r * 64 + c] = e; dp += e;
        }
        red[t] = dp; __syncthreads();
        float inv = 1.0f / (red[c * 4] + red[c * 4 + 1] + red[c * 4 + 2] + red[c * 4 + 3]);
        for (int r = rq * 16; r < rq * 16 + 16; r++) Ss[r * 64 + c] *= inv;
        __syncthreads();
    }

    // ---- stage 4: agg = S^T x ; x_c = mean_h leaky(x + agg @ lW[h]) ----
    float* agg = h1b;
    {
        unsigned long long acc[8][2];
        #pragma unroll
        for (int r = 0; r < 8; r++) { acc[r][0] = 0ull; acc[r][1] = 0ull; }
        gsegT<2>(Ss, xs, 128, 64, ty, txc, acc);
        estore<2, 0>(agg, 128, ty, txc, acc);
    }
    __syncthreads();
    {
        unsigned long long a0[8][2], a1[8][2];
        #pragma unroll
        for (int r = 0; r < 8; r++) { a0[r][0]=0ull;a0[r][1]=0ull;a1[r][0]=0ull;a1[r][1]=0ull; }
        gseg<2>(agg, 128, lW,         128, 128, ty, txc, a0);
        gseg<2>(agg, 128, lW + 16384, 128, 128, ty, txc, a1);
        __syncthreads();
        #pragma unroll
        for (int r = 0; r < 8; r++) {
            int row = ty * 8 + r;
            #pragma unroll
            for (int j = 0; j < 2; j++) {
                float l0, h0, l1, h1v;
                unpackf2(a0[r][j], l0, h0);
                unpackf2(a1[r][j], l1, h1v);
                int col = txc * 4 + 2 * j;
                float x0 = xs[row * 128 + col], x1 = xs[row * 128 + col + 1];
                float vlo = 0.5f * (leaky(x0 + l0) + leaky(x0 + l1));
                float vhi = 0.5f * (leaky(x1 + h0) + leaky(x1 + h1v));
                *(float2*)(axc + row * 128 + col) = make_float2(vlo, vhi);
            }
        }
    }
    __syncthreads();

    // ---- stage 5: q2 = hop2(x_c) for rank0 (rank1 keeps qt in qs) ----
    if (rank == 0) {
        float* tmp = h1b;
        unsigned long long acc[8][2];
        #pragma unroll
        for (int r = 0; r < 8; r++) { acc[r][0] = 0ull; acc[r][1] = 0ull; }
        gseg<2>(Ms, 64, axc, 128, 64, ty, txc, acc);
        estore<2, 0>(tmp, 128, ty, txc, acc);
        __syncthreads();
        unsigned long long acc2[8][2];
        #pragma unroll
        for (int r = 0; r < 8; r++) { acc2[r][0] = 0ull; acc2[r][1] = 0ull; }
        gseg<2>(Ms, 64, tmp, 128, 64, ty, txc, acc2);
        estore<2, 0>(qs, 128, ty, txc, acc2);
        __syncthreads();
    }

    // ---- stage 6: attention #2 (head = 2 + rank), kv = x_c -> gown ----
    attention(sm, t, ty, txc, axc, qs, h1b, 2 + (int)rank, Wk, W2, W3, gown);

    cluster_sync();
    if (t < 64) gpeer[t] = dsread(gown + t, rank ^ 1);
    __syncthreads();

    // ---- stage 7: cluster score softmax + top-52 (duplicated per rank) ----
    if (t < 64) sscore[t] = gown[t] + gpeer[t];
    __syncthreads();
    softmax64(sscore, red, t);
    if (t < 32) {
        float v0 = sscore[t], v1 = sscore[t + 32];
        for (int j = 0; j < KK; j++) {
            float mv = v0; int mi = t;
            if (v1 > mv) { mv = v1; mi = t + 32; }
            #pragma unroll
            for (int off = 16; off; off >>= 1) {
                float ov = __shfl_xor_sync(0xffffffffu, mv, off);
                int   oi = __shfl_xor_sync(0xffffffffu, mi, off);
                if (ov > mv || (ov == mv && oi < mi)) { mv = ov; mi = oi; }
            }
            if (t == 0) permsh[j] = mi;
            if (mi < 32) { if (t == mi) v0 = -3.0e38f; }
            else         { if (t == mi - 32) v1 = -3.0e38f; }
        }
    }
    __syncthreads();

    // ---- stage 8: outputs ----
    // x_out + meta (rank0 only)
    if (rank == 0) {
        for (int i = t; i < KK * 32; i += 256) {
            int e = i >> 5, c4 = (i & 31) * 4;
            int p = permsh[e];
            float sc = sscore[p];
            float4 xv = *(const float4*)(xs + p * 128 + c4);
            *(float4*)(outx + (size_t)(b * KK + e) * 128 + c4) =
                make_float4(xv.x * sc, xv.y * sc, xv.z * sc, xv.w * sc);
        }
        if (t < KK) {
            int p = permsh[t];
            outb[b * KK + t] = (float)b;
            outp[b * KK + t] = (float)(b * 64 + p);
        }
    }

    // A2 block: T = A_d @ S_sel ; A2 = S_sel^T @ T (rows split by rank)
    float* T = h1b;   // 64*52 floats
    for (int i = t; i < 64 * KK; i += 256) {
        int r = i / KK, j = i - r * KK;
        int cj = permsh[j];
        float acc = 0.0f;
        #pragma unroll
        for (int c = 0; c < 64; c++) acc += Ms[c * 64 + r] * Ss[c * 64 + cj];
        T[i] = acc;
    }
    __syncthreads();
    for (int o = t; o < 26 * KK; o += 256) {
        int il = o / KK, j = o - il * KK;
        int i = (int)rank * 26 + il;
        float v;
        if (i == j) v = 1.0f;
        else {
            int ci = permsh[i];
            v = 0.0f;
            #pragma unroll
            for (int r = 0; r < 64; r++) v += Ss[r * 64 + ci] * T[r * KK + j];
        }
        outA2[(size_t)(b * KK + i) * NK + (size_t)(b * KK + j)] = v;
    }
}

// =======================================================================
extern "C" void kernel_launch(void* const* d_in, const int* in_sizes, int n_in,
                              void* d_out, int out_size) {
    const float* x   = (const float*)d_in[0];
    const int*   ei  = (const int*)d_in[1];
    const float* ewt = (const float*)d_in[2];
    const float* tx  = (const float*)d_in[3];
    const float* Wk  = (const float*)d_in[5];
    const float* W1  = (const float*)d_in[6];
    const float* W2  = (const float*)d_in[7];
    const float* W3  = (const float*)d_in[8];
    const float* lW  = (const float*)d_in[9];
    float* out = (float*)d_out;

    float* out_x    = out;
    float* out_A2   = out + (size_t)NK * HH;
    float* out_bat  = out + (size_t)NK * HH + (size_t)NK * NK;
    float* out_perm = out_bat + NK;

    static int smem_set = 0;
    if (!smem_set) {
        cudaFuncSetAttribute(mega_k, cudaFuncAttributeMaxDynamicSharedMemorySize, SM_BYTES);
        smem_set = 1;
    }

    fold_k<<<(4 * 384 * 256 + 255) / 256, 256>>>(W1);
    cudaMemsetAsync(out_A2, 0, (size_t)NK * NK * sizeof(float));
    mega_k<<<2 * BB, 256, SM_BYTES>>>(x, ei, ewt, tx, Wk, W2, W3, lW,
                                      out_x, out_A2, out_bat, out_perm);
}